// round 9
// baseline (speedup 1.0000x reference)
#include <cuda_runtime.h>
#include <cstdint>

#define B_ 8
#define N_ 256
#define L_ 48
#define F_ 96
#define LF (L_*F_)
#define NSTRIP 32 // i-strips for k_reduce (8 rows each)

#define ASTR 100  // A smem row stride in floats (50 float2), banks 4g mod 32 distinct
#define BSTR 100  // B smem row stride in floats (f-major, k-interleaved cols)

// ---------------- scratch (no allocation allowed) ----------------
__device__ float g_rowsum [B_*N_*L_];
__device__ float g_diag   [B_*N_*L_];
__device__ float g_colpart[B_*NSTRIP*N_*L_];
__device__ float g_stripT [B_*NSTRIP*L_];
__device__ float g_stripS [B_*NSTRIP*L_];
__device__ float g_diagA  [B_*N_*F_];
__device__ float g_bi     [B_*N_*F_];
__device__ float g_bjs    [B_*N_*F_];

// ---------------- tf32 helpers ----------------
__device__ __forceinline__ float tf32r(float v){
    uint32_t r; asm("cvt.rna.tf32.f32 %0, %1;" : "=r"(r) : "f"(v));
    return __uint_as_float(r);
}
__device__ __forceinline__ void mma_tf32(float* c, const uint32_t* a, const uint32_t* b){
    asm volatile(
        "mma.sync.aligned.m16n8k8.row.col.f32.tf32.tf32.f32 "
        "{%0,%1,%2,%3}, {%4,%5,%6,%7}, {%8,%9}, {%0,%1,%2,%3};"
        : "+f"(c[0]), "+f"(c[1]), "+f"(c[2]), "+f"(c[3])
        : "r"(a[0]), "r"(a[1]), "r"(a[2]), "r"(a[3]), "r"(b[0]), "r"(b[1]));
}

// k-interleave within each k8 group: b -> (b&3)*2 + (b>>2)
__device__ __forceinline__ int kcol(int k){
    return (k & ~7) + ((k & 3)*2) + ((k >> 2) & 1);
}

// ================= K0: fused reductions, 2 barriers =================
// grid (NSTRIP, B). 384 threads: q = t/12 (32 j-groups), lq = (t%12)*4.
__global__ __launch_bounds__(384) void k_reduce(const float* __restrict__ x){
    const int istrip = blockIdx.x, b = blockIdx.y;
    const int i0 = istrip*8;
    const int t = threadIdx.x;
    const int q = t/12, lq = (t%12)*4;

    extern __shared__ float smr[];
    float* rp = smr;               // [8][32][49]
    float* rs = rp + 8*32*49;      // [8][48]
    float* dgs = rs + 8*48;        // [8][48]

    float ca[8][4];
    #pragma unroll
    for (int jj = 0; jj < 8; jj++){ ca[jj][0]=0.f; ca[jj][1]=0.f; ca[jj][2]=0.f; ca[jj][3]=0.f; }

    const float* xb = x + ((size_t)b)*N_*N_*L_;

    #pragma unroll
    for (int ii = 0; ii < 8; ii++){
        const float* xr = xb + (size_t)(i0+ii)*N_*L_;
        float r0=0.f, r1=0.f, r2=0.f, r3=0.f;
        #pragma unroll
        for (int jj = 0; jj < 8; jj++){
            float4 v = *(const float4*)(xr + (q + 32*jj)*L_ + lq);
            ca[jj][0]+=v.x; ca[jj][1]+=v.y; ca[jj][2]+=v.z; ca[jj][3]+=v.w;
            r0+=v.x; r1+=v.y; r2+=v.z; r3+=v.w;
        }
        float* rpp = rp + (ii*32 + q)*49 + lq;
        rpp[0]=r0; rpp[1]=r1; rpp[2]=r2; rpp[3]=r3;
    }
    __syncthreads();

    // 384 threads = 8 ii x 48 l
    {
        const int ii = t / 48, l = t % 48;
        float s = 0.f;
        #pragma unroll
        for (int qq = 0; qq < 32; qq++) s += rp[(ii*32 + qq)*49 + l];
        const int i = i0 + ii;
        g_rowsum[(b*N_+i)*L_ + l] = s;
        rs[ii*48 + l] = s;
        const float dv = xb[((size_t)i*N_ + i)*L_ + l];
        g_diag[(b*N_+i)*L_ + l] = dv;
        dgs[ii*48 + l] = dv;
    }
    __syncthreads();
    if (t < 48){
        float sT = 0.f, sS = 0.f;
        #pragma unroll
        for (int ii = 0; ii < 8; ii++){ sT += dgs[ii*48 + t]; sS += rs[ii*48 + t]; }
        g_stripT[(b*NSTRIP+istrip)*L_ + t] = sT;
        g_stripS[(b*NSTRIP+istrip)*L_ + t] = sS;
    }
    // colsum partials (float4)
    #pragma unroll
    for (int jj = 0; jj < 8; jj++){
        float* cp = g_colpart + ((size_t)((b*NSTRIP+istrip)*N_ + q + 32*jj))*L_ + lq;
        *(float4*)cp = make_float4(ca[jj][0], ca[jj][1], ca[jj][2], ca[jj][3]);
    }
}

// ================= K1: per-node projections (8 nodes/block) + scalars =================
__global__ __launch_bounds__(96) void k_node(const float* __restrict__ w){
    const int b = blockIdx.y;
    const int n0 = blockIdx.x * 8;
    const int t = threadIdx.x;

    __shared__ float d_[8][48], r_[8][48], c_[8][48];
    __shared__ float tr[48], ts[48];

    for (int idx = t; idx < 8*48; idx += 96){
        const int nn = idx / 48, l = idx % 48;
        const int base = (b*N_ + n0 + nn)*L_ + l;
        d_[nn][l] = g_diag  [base];
        r_[nn][l] = g_rowsum[base];
        float s = 0.f;
        #pragma unroll
        for (int st = 0; st < NSTRIP; st++)
            s += g_colpart[((size_t)((b*NSTRIP+st)*N_ + n0 + nn))*L_ + l];
        c_[nn][l] = s;
    }
    if (t < 48){
        float a = 0.f, s = 0.f;
        #pragma unroll
        for (int st = 0; st < NSTRIP; st++){
            a += g_stripT[(b*NSTRIP+st)*L_ + t];
            s += g_stripS[(b*NSTRIP+st)*L_ + t];
        }
        tr[t] = a; ts[t] = s;
    }
    __syncthreads();

    float aA[8], aJ[8], aI[8];
    #pragma unroll
    for (int nn = 0; nn < 8; nn++){ aA[nn]=0.f; aJ[nn]=0.f; aI[nn]=0.f; }
    float ds = 0.f, sc = 0.f;

    for (int l = 0; l < 48; l++){
        const float* wl = w + l*F_ + t;
        const float w0  = __ldg(wl);
        const float w1  = __ldg(wl +    LF);
        const float w2  = __ldg(wl +  2*LF);
        const float w3  = __ldg(wl +  3*LF);
        const float w4  = __ldg(wl +  4*LF);
        const float w5  = __ldg(wl +  5*LF);
        const float w6  = __ldg(wl +  6*LF);
        const float w7  = __ldg(wl +  7*LF);
        const float w8  = __ldg(wl +  8*LF);
        const float w9  = __ldg(wl +  9*LF);
        const float w10 = __ldg(wl + 10*LF);
        const float w13 = __ldg(wl + 13*LF);
        const float w14 = __ldg(wl + 14*LF);
        const float trl = tr[l], tsl = ts[l];
        ds += trl*w3  + tsl*w4;
        sc += trl*w13 + tsl*w14;
        #pragma unroll
        for (int nn = 0; nn < 8; nn++){
            const float dd = d_[nn][l], rr = r_[nn][l], cc = c_[nn][l];
            aA[nn] += dd*w0 + rr*w1 + cc*w2;
            aJ[nn] += dd*w5 + rr*w6 + cc*w7;
            aI[nn] += dd*w8 + rr*w9 + cc*w10;
        }
    }
    #pragma unroll
    for (int nn = 0; nn < 8; nn++){
        const int o = (b*N_ + n0 + nn)*F_ + t;
        g_diagA[o] = aA[nn] + ds;
        g_bjs  [o] = aJ[nn] + sc;
        g_bi   [o] = aI[nn];
    }
}

// ================= K2: main kernel — tf32 mma.sync, 1024 threads =================
// 16x16 (i,j) tile: M=256, N=96, K=96. 32 warps, warp tile M32 x N24.
// k-interleaved smem: frag loads are ld.shared.v2 (A pairs and B pairs adjacent).
__global__ __launch_bounds__(1024, 1)
void k_main(const float* __restrict__ x, const float* __restrict__ w,
            float* __restrict__ out){
    const int jt = blockIdx.x, it = blockIdx.y, b = blockIdx.z;
    const int i0 = it*16, j0 = jt*16;
    const int tid = threadIdx.x;

    extern __shared__ float sm[];
    float* As    = sm;                 // [256][ASTR], k-interleaved cols
    float* Bs    = As + 256*ASTR;      // [96 f][BSTR], k-interleaved cols
    float* bis   = Bs + 96*BSTR;       // [16][96]
    float* bjs_s = bis + 16*96;        // [16][96]

    const float* xb = x + ((size_t)b)*N_*N_*L_;

    // ---- stage A direct half (k < 48), interleaved cols ----
    for (int idx = tid; idx < 3072; idx += 1024){
        const int p = idx / 12, c = idx % 12;       // c-th float4 of the row
        const int ti = p >> 4, tj = p & 15;
        float4 v = *(const float4*)(xb + ((size_t)(i0+ti)*N_ + (j0+tj))*L_ + c*4);
        float* dst = As + p*ASTR + (c >> 1)*8 + (c & 1);
        dst[0]=tf32r(v.x); dst[2]=tf32r(v.y); dst[4]=tf32r(v.z); dst[6]=tf32r(v.w);
    }
    // ---- stage A transposed half (k >= 48) ----
    for (int idx = tid; idx < 3072; idx += 1024){
        const int p = idx / 12, c = idx % 12;
        const int ti = p >> 4, tj = p & 15;
        float4 v = *(const float4*)(xb + ((size_t)(j0+tj)*N_ + (i0+ti))*L_ + c*4);
        float* dst = As + p*ASTR + 48 + (c >> 1)*8 + (c & 1);
        dst[0]=tf32r(v.x); dst[2]=tf32r(v.y); dst[4]=tf32r(v.z); dst[6]=tf32r(v.w);
    }
    // ---- stage B transposed+interleaved: Bs[f][kcol(k)] = (k<48 ? w12 : w11) ----
    {
        const float* w12g = w + 12*LF;
        const float* w11g = w + 11*LF;
        for (int idx = tid; idx < 96*24; idx += 1024){
            const int k = idx / 24, f4 = (idx % 24)*4;
            const float* src = (k < 48) ? (w12g + k*F_ + f4) : (w11g + (k-48)*F_ + f4);
            float4 v = *(const float4*)src;
            const int kc = kcol(k);
            Bs[(f4+0)*BSTR + kc] = tf32r(v.x);
            Bs[(f4+1)*BSTR + kc] = tf32r(v.y);
            Bs[(f4+2)*BSTR + kc] = tf32r(v.z);
            Bs[(f4+3)*BSTR + kc] = tf32r(v.w);
        }
    }
    // ---- stage bias tiles ----
    for (int idx = tid; idx < 16*F_; idx += 1024){
        const int r = idx / F_, f = idx % F_;
        bis  [idx] = g_bi [(b*N_ + i0 + r)*F_ + f];
        bjs_s[idx] = g_bjs[(b*N_ + j0 + r)*F_ + f];
    }
    __syncthreads();

    // ---- warp mapping: 32 warps = 8 mw x 4 nw; warp tile M32 x N24 ----
    const int wid = tid >> 5, lane = tid & 31;
    const int mw = wid >> 2, nw = wid & 3;
    const int g = lane >> 2, t = lane & 3;
    const int mb = mw*32, nb = nw*24;

    float acc[2][3][4];
    #pragma unroll
    for (int fm = 0; fm < 2; fm++)
        #pragma unroll
        for (int tl = 0; tl < 3; tl++)
            #pragma unroll
            for (int qq = 0; qq < 4; qq++) acc[fm][tl][qq] = 0.f;

    const float2* A2 = (const float2*)As;          // row stride ASTR/2 = 50
    const float2* B2 = (const float2*)Bs;          // row stride 50
    const float2* Ar0 = A2 + (size_t)(mb + g)*50 + t;
    const float2* Ar1 = Ar0 + 8*50;
    const float2* Bb  = B2 + (size_t)(nb + g)*50 + t;

    #pragma unroll
    for (int ks = 0; ks < 12; ks++){
        const int kf = ks*4;
        uint32_t a[2][4];
        #pragma unroll
        for (int fm = 0; fm < 2; fm++){
            float2 p0 = Ar0[fm*16*50 + kf];   // {a0, a2}
            float2 p1 = Ar1[fm*16*50 + kf];   // {a1, a3}
            a[fm][0] = __float_as_uint(p0.x);
            a[fm][1] = __float_as_uint(p1.x);
            a[fm][2] = __float_as_uint(p0.y);
            a[fm][3] = __float_as_uint(p1.y);
        }
        uint32_t bb[3][2];
        #pragma unroll
        for (int tl = 0; tl < 3; tl++){
            float2 qv = Bb[tl*8*50 + kf];     // {b0, b1}
            bb[tl][0] = __float_as_uint(qv.x);
            bb[tl][1] = __float_as_uint(qv.y);
        }
        #pragma unroll
        for (int fm = 0; fm < 2; fm++)
            #pragma unroll
            for (int tl = 0; tl < 3; tl++)
                mma_tf32(acc[fm][tl], a[fm], bb[tl]);
    }

    // ---- epilogue ----
    #pragma unroll
    for (int fm = 0; fm < 2; fm++){
        const int ti_l = mw*2 + fm;
        const int gi = i0 + ti_l;
        const float* irow = bis + ti_l*F_;
        const float* drow = g_diagA + ((size_t)(b*N_ + gi))*F_;
        #pragma unroll
        for (int half = 0; half < 2; half++){
            const int tj = half*8 + g;
            const bool dg = (ti_l == tj) && (it == jt);
            float* orow = out + (((size_t)(b*N_ + gi))*N_ + (j0 + tj))*F_;
            const float* jrow = bjs_s + tj*F_;
            #pragma unroll
            for (int tl = 0; tl < 3; tl++){
                const int f = nb + tl*8 + 2*t;
                float v0 = acc[fm][tl][half*2+0] + irow[f]   + jrow[f];
                float v1 = acc[fm][tl][half*2+1] + irow[f+1] + jrow[f+1];
                if (dg){ v0 += __ldg(drow + f); v1 += __ldg(drow + f + 1); }
                *(float2*)(orow + f) = make_float2(v0, v1);
            }
        }
    }
}

// ---------------- launch ----------------
extern "C" void kernel_launch(void* const* d_in, const int* in_sizes, int n_in,
                              void* d_out, int out_size){
    const float* x = (const float*)d_in[0];
    const float* w = (const float*)d_in[1];
    float* out = (float*)d_out;
    (void)in_sizes; (void)n_in; (void)out_size;

    const size_t smr = (size_t)(8*32*49 + 2*8*48) * sizeof(float);   // 53248 B
    cudaFuncSetAttribute(k_reduce, cudaFuncAttributeMaxDynamicSharedMemorySize, (int)smr);
    k_reduce<<<dim3(NSTRIP, B_), 384, smr>>>(x);

    k_node<<<dim3(32, B_), 96>>>(w);

    const size_t smm = (size_t)(256*ASTR + 96*BSTR + 2*16*96) * sizeof(float); // 153088 B
    cudaFuncSetAttribute(k_main, cudaFuncAttributeMaxDynamicSharedMemorySize, (int)smm);
    k_main<<<dim3(16, 16, B_), 1024, smm>>>(x, w, out);
}

// round 10
// speedup vs baseline: 1.3321x; 1.3321x over previous
#include <cuda_runtime.h>
#include <cuda_bf16.h>
#include <cstdint>

#define B_ 8
#define N_ 256
#define L_ 48
#define F_ 96
#define LF (L_*F_)
#define NSTRIP 32  // i-strips for k_reduce (8 rows each)

#define AROW 104   // A smem row stride in bf16 (208 B = 26 x 8B units, perfect 2-way banks)
#define BROW 104   // B smem row stride in bf16
#define GPERS 152  // persistent grid (GB300: 152 SMs)

// ---------------- scratch (no allocation allowed) ----------------
__device__ float g_rowsum [B_*N_*L_];
__device__ float g_diag   [B_*N_*L_];
__device__ float g_colpart[B_*NSTRIP*N_*L_];
__device__ float g_stripT [B_*NSTRIP*L_];
__device__ float g_stripS [B_*NSTRIP*L_];
__device__ float g_diagA  [B_*N_*F_];
__device__ float g_bi     [B_*N_*F_];
__device__ float g_bjs    [B_*N_*F_];

// ---------------- bf16 mma helper ----------------
__device__ __forceinline__ void mma_bf16(float* c, const uint32_t* a, const uint32_t* b){
    asm volatile(
        "mma.sync.aligned.m16n8k16.row.col.f32.bf16.bf16.f32 "
        "{%0,%1,%2,%3}, {%4,%5,%6,%7}, {%8,%9}, {%0,%1,%2,%3};"
        : "+f"(c[0]), "+f"(c[1]), "+f"(c[2]), "+f"(c[3])
        : "r"(a[0]), "r"(a[1]), "r"(a[2]), "r"(a[3]), "r"(b[0]), "r"(b[1]));
}

// k-interleave within each 16-col group: order [0,1,8,9,2,3,10,11,4,5,12,13,6,7,14,15]
__device__ __forceinline__ int kpos16(int k){
    return (k & ~15) + (((k & 7) >> 1) << 2) + (((k >> 3) & 1) << 1) + (k & 1);
}
// position of an even k (start of a bf162 pair)
__device__ __forceinline__ int kposPair(int kk){
    return (kk & ~15) + (((kk & 7) >> 1) << 2) + (((kk >> 3) & 1) << 1);
}

// ================= K0: fused reductions, 2 barriers =================
__global__ __launch_bounds__(384) void k_reduce(const float* __restrict__ x){
    const int istrip = blockIdx.x, b = blockIdx.y;
    const int i0 = istrip*8;
    const int t = threadIdx.x;
    const int q = t/12, lq = (t%12)*4;

    extern __shared__ float smr[];
    float* rp = smr;               // [8][32][49]
    float* rs = rp + 8*32*49;      // [8][48]
    float* dgs = rs + 8*48;        // [8][48]

    float ca[8][4];
    #pragma unroll
    for (int jj = 0; jj < 8; jj++){ ca[jj][0]=0.f; ca[jj][1]=0.f; ca[jj][2]=0.f; ca[jj][3]=0.f; }

    const float* xb = x + ((size_t)b)*N_*N_*L_;

    #pragma unroll
    for (int ii = 0; ii < 8; ii++){
        const float* xr = xb + (size_t)(i0+ii)*N_*L_;
        float r0=0.f, r1=0.f, r2=0.f, r3=0.f;
        #pragma unroll
        for (int jj = 0; jj < 8; jj++){
            float4 v = *(const float4*)(xr + (q + 32*jj)*L_ + lq);
            ca[jj][0]+=v.x; ca[jj][1]+=v.y; ca[jj][2]+=v.z; ca[jj][3]+=v.w;
            r0+=v.x; r1+=v.y; r2+=v.z; r3+=v.w;
        }
        float* rpp = rp + (ii*32 + q)*49 + lq;
        rpp[0]=r0; rpp[1]=r1; rpp[2]=r2; rpp[3]=r3;
    }
    __syncthreads();
    {
        const int ii = t / 48, l = t % 48;
        float s = 0.f;
        #pragma unroll
        for (int qq = 0; qq < 32; qq++) s += rp[(ii*32 + qq)*49 + l];
        const int i = i0 + ii;
        g_rowsum[(b*N_+i)*L_ + l] = s;
        rs[ii*48 + l] = s;
        const float dv = xb[((size_t)i*N_ + i)*L_ + l];
        g_diag[(b*N_+i)*L_ + l] = dv;
        dgs[ii*48 + l] = dv;
    }
    __syncthreads();
    if (t < 48){
        float sT = 0.f, sS = 0.f;
        #pragma unroll
        for (int ii = 0; ii < 8; ii++){ sT += dgs[ii*48 + t]; sS += rs[ii*48 + t]; }
        g_stripT[(b*NSTRIP+istrip)*L_ + t] = sT;
        g_stripS[(b*NSTRIP+istrip)*L_ + t] = sS;
    }
    #pragma unroll
    for (int jj = 0; jj < 8; jj++){
        float* cp = g_colpart + ((size_t)((b*NSTRIP+istrip)*N_ + q + 32*jj))*L_ + lq;
        *(float4*)cp = make_float4(ca[jj][0], ca[jj][1], ca[jj][2], ca[jj][3]);
    }
}

// ================= K1: per-node projections + scalars =================
__global__ __launch_bounds__(96) void k_node(const float* __restrict__ w){
    const int b = blockIdx.y;
    const int n0 = blockIdx.x * 8;
    const int t = threadIdx.x;

    __shared__ float d_[8][48], r_[8][48], c_[8][48];
    __shared__ float tr[48], ts[48];

    for (int idx = t; idx < 8*48; idx += 96){
        const int nn = idx / 48, l = idx % 48;
        const int base = (b*N_ + n0 + nn)*L_ + l;
        d_[nn][l] = g_diag  [base];
        r_[nn][l] = g_rowsum[base];
        float s = 0.f;
        #pragma unroll
        for (int st = 0; st < NSTRIP; st++)
            s += g_colpart[((size_t)((b*NSTRIP+st)*N_ + n0 + nn))*L_ + l];
        c_[nn][l] = s;
    }
    if (t < 48){
        float a = 0.f, s = 0.f;
        #pragma unroll
        for (int st = 0; st < NSTRIP; st++){
            a += g_stripT[(b*NSTRIP+st)*L_ + t];
            s += g_stripS[(b*NSTRIP+st)*L_ + t];
        }
        tr[t] = a; ts[t] = s;
    }
    __syncthreads();

    float aA[8], aJ[8], aI[8];
    #pragma unroll
    for (int nn = 0; nn < 8; nn++){ aA[nn]=0.f; aJ[nn]=0.f; aI[nn]=0.f; }
    float ds = 0.f, sc = 0.f;

    for (int l = 0; l < 48; l++){
        const float* wl = w + l*F_ + t;
        const float w0  = __ldg(wl);
        const float w1  = __ldg(wl +    LF);
        const float w2  = __ldg(wl +  2*LF);
        const float w3  = __ldg(wl +  3*LF);
        const float w4  = __ldg(wl +  4*LF);
        const float w5  = __ldg(wl +  5*LF);
        const float w6  = __ldg(wl +  6*LF);
        const float w7  = __ldg(wl +  7*LF);
        const float w8  = __ldg(wl +  8*LF);
        const float w9  = __ldg(wl +  9*LF);
        const float w10 = __ldg(wl + 10*LF);
        const float w13 = __ldg(wl + 13*LF);
        const float w14 = __ldg(wl + 14*LF);
        const float trl = tr[l], tsl = ts[l];
        ds += trl*w3  + tsl*w4;
        sc += trl*w13 + tsl*w14;
        #pragma unroll
        for (int nn = 0; nn < 8; nn++){
            const float dd = d_[nn][l], rr = r_[nn][l], cc = c_[nn][l];
            aA[nn] += dd*w0 + rr*w1 + cc*w2;
            aJ[nn] += dd*w5 + rr*w6 + cc*w7;
            aI[nn] += dd*w8 + rr*w9 + cc*w10;
        }
    }
    #pragma unroll
    for (int nn = 0; nn < 8; nn++){
        const int o = (b*N_ + n0 + nn)*F_ + t;
        g_diagA[o] = aA[nn] + ds;
        g_bjs  [o] = aJ[nn] + sc;
        g_bi   [o] = aI[nn];
    }
}

// ================= K2: persistent bf16 mma.sync kernel =================
// grid GPERS x 1024 thr. Each block owns ~13-14 contiguous tiles (b,it,jt).
// Per tile: M=256, N=96, K=96 GEMM (A = [x_dir | x_trans] bf16, B = [w12;w11] bf16).
// 32 warps, warp tile M32 x N24, m16n8k16.
__global__ __launch_bounds__(1024, 1)
void k_main(const float* __restrict__ x, const float* __restrict__ w,
            float* __restrict__ out){
    const int tid = threadIdx.x;
    const int bk = blockIdx.x;

    extern __shared__ char smraw[];
    __nv_bfloat16* Ab = (__nv_bfloat16*)smraw;            // [256][AROW]
    __nv_bfloat16* Bb = Ab + 256*AROW;                    // [96][BROW]
    float* bis   = (float*)(Bb + 96*BROW);                // [16][96]
    float* bjs_s = bis + 16*96;                           // [16][96]

    // ---- stage B once: Bb[f][kpos16(k)] = (k<48 ? w12[k][f] : w11[k-48][f]) ----
    {
        const float* w12g = w + 12*LF;
        const float* w11g = w + 11*LF;
        for (int idx = tid; idx < 96*96; idx += 1024){
            const int k = idx / 96, f = idx % 96;
            const float v = (k < 48) ? __ldg(w12g + k*F_ + f) : __ldg(w11g + (k-48)*F_ + f);
            Bb[f*BROW + kpos16(k)] = __float2bfloat16(v);
        }
    }

    // tile range: 2048 tiles over GPERS blocks (first 72 get 14, rest 13)
    const int base = bk*13 + (bk < 72 ? bk : 72);
    const int cnt  = 13 + (bk < 72 ? 1 : 0);

    // ---- helpers to decode & stage ----
    // thread's staging slots: idx = tid + q*1024 over 3072 float4 per half
    // p = idx/12 (row 0..255), c = idx%12 (float4 within 48-col half)

    // prologue: fully stage tile 'base'
    {
        const int tl0 = base;
        const int b = tl0 >> 8, r = tl0 & 255, it = r >> 4, jt = r & 15;
        const int i0 = it*16, j0 = jt*16;
        const float* xb = x + ((size_t)b)*N_*N_*L_;
        #pragma unroll
        for (int q = 0; q < 3; q++){
            const int idx = tid + q*1024;
            const int p = idx / 12, c = idx % 12;
            const int ti = p >> 4, tj = p & 15;
            // direct half
            float4 v = *(const float4*)(xb + ((size_t)(i0+ti)*N_ + (j0+tj))*L_ + c*4);
            int posA = kposPair(c*4);
            __nv_bfloat16* dst = Ab + p*AROW + posA;
            *(__nv_bfloat162*)dst       = __floats2bfloat162_rn(v.x, v.y);
            *(__nv_bfloat162*)(dst + 4) = __floats2bfloat162_rn(v.z, v.w);
            // trans half
            float4 u = *(const float4*)(xb + ((size_t)(j0+tj)*N_ + (i0+ti))*L_ + c*4);
            int posB = 48 + posA;
            __nv_bfloat16* dst2 = Ab + p*AROW + posB;
            *(__nv_bfloat162*)dst2       = __floats2bfloat162_rn(u.x, u.y);
            *(__nv_bfloat162*)(dst2 + 4) = __floats2bfloat162_rn(u.z, u.w);
        }
        #pragma unroll
        for (int q = 0; q < 3; q++){
            const int idx = tid + q*1024;   // 0..3071
            if (idx < 1536){
                const int rr = idx / 96, f = idx % 96;
                bis[idx] = g_bi[(b*N_ + i0 + rr)*F_ + f];
            } else {
                const int ix = idx - 1536;
                const int rr = ix / 96, f = ix % 96;
                bjs_s[ix] = g_bjs[(b*N_ + j0 + rr)*F_ + f];
            }
        }
    }
    __syncthreads();

    // ---- warp mapping ----
    const int wid = tid >> 5, lane = tid & 31;
    const int mw = wid >> 2, nw = wid & 3;       // 8 x 4
    const int g = lane >> 2, t4 = lane & 3;
    const int mb = mw*32, nbv = nw*24;

    const uint2* A8 = (const uint2*)Ab;          // row stride 26 (8B units)
    const uint2* B8 = (const uint2*)Bb;

    for (int s = 0; s < cnt; s++){
        const int tl = base + s;
        const int b = tl >> 8, r = tl & 255, it = r >> 4, jt = r & 15;
        const int i0 = it*16, j0 = jt*16;

        // prefetch next tile's DIRECT half into registers (hidden under MMA+epilogue)
        const bool hasNext = (s + 1 < cnt);
        float4 nx[3];
        int nb_=0, ni0=0, nj0=0;
        if (hasNext){
            const int tn = tl + 1;
            nb_ = tn >> 8; const int rn = tn & 255; ni0 = (rn >> 4)*16; nj0 = (rn & 15)*16;
            const float* xbn = x + ((size_t)nb_)*N_*N_*L_;
            #pragma unroll
            for (int q = 0; q < 3; q++){
                const int idx = tid + q*1024;
                const int p = idx / 12, c = idx % 12;
                const int ti = p >> 4, tj = p & 15;
                nx[q] = *(const float4*)(xbn + ((size_t)(ni0+ti)*N_ + (nj0+tj))*L_ + c*4);
            }
        }

        // ---- MMA mainloop: 6 k16 steps ----
        float acc[2][3][4];
        #pragma unroll
        for (int fm = 0; fm < 2; fm++)
            #pragma unroll
            for (int tl2 = 0; tl2 < 3; tl2++)
                #pragma unroll
                for (int qq = 0; qq < 4; qq++) acc[fm][tl2][qq] = 0.f;

        #pragma unroll
        for (int ks = 0; ks < 6; ks++){
            const int kofs = ks*4 + t4;
            uint32_t a[2][4];
            #pragma unroll
            for (int fm = 0; fm < 2; fm++){
                uint2 u = A8[(size_t)(mb + fm*16 + g    )*26 + kofs];
                uint2 v = A8[(size_t)(mb + fm*16 + g + 8)*26 + kofs];
                a[fm][0] = u.x; a[fm][1] = v.x; a[fm][2] = u.y; a[fm][3] = v.y;
            }
            uint32_t bb[3][2];
            #pragma unroll
            for (int tl2 = 0; tl2 < 3; tl2++){
                uint2 qv = B8[(size_t)(nbv + tl2*8 + g)*26 + kofs];
                bb[tl2][0] = qv.x; bb[tl2][1] = qv.y;
            }
            #pragma unroll
            for (int fm = 0; fm < 2; fm++)
                #pragma unroll
                for (int tl2 = 0; tl2 < 3; tl2++)
                    mma_bf16(acc[fm][tl2], a[fm], bb[tl2]);
        }

        // ---- epilogue ----
        #pragma unroll
        for (int fm = 0; fm < 2; fm++){
            const int ti_l = mw*2 + fm;
            const int gi = i0 + ti_l;
            const float* irow = bis + ti_l*F_;
            const float* drow = g_diagA + ((size_t)(b*N_ + gi))*F_;
            #pragma unroll
            for (int half = 0; half < 2; half++){
                const int tj = half*8 + g;
                const bool dg = (ti_l == tj) && (it == jt);
                float* orow = out + (((size_t)(b*N_ + gi))*N_ + (j0 + tj))*F_;
                const float* jrow = bjs_s + tj*F_;
                #pragma unroll
                for (int tl2 = 0; tl2 < 3; tl2++){
                    const int f = nbv + tl2*8 + 2*t4;
                    float v0 = acc[fm][tl2][half*2+0] + irow[f]   + jrow[f];
                    float v1 = acc[fm][tl2][half*2+1] + irow[f+1] + jrow[f+1];
                    if (dg){ v0 += __ldg(drow + f); v1 += __ldg(drow + f + 1); }
                    *(float2*)(orow + f) = make_float2(v0, v1);
                }
            }
        }
        __syncthreads();   // all smem reads of tile s done

        if (hasNext){
            // store prefetched direct half
            #pragma unroll
            for (int q = 0; q < 3; q++){
                const int idx = tid + q*1024;
                const int p = idx / 12, c = idx % 12;
                int posA = kposPair(c*4);
                __nv_bfloat16* dst = Ab + p*AROW + posA;
                *(__nv_bfloat162*)dst       = __floats2bfloat162_rn(nx[q].x, nx[q].y);
                *(__nv_bfloat162*)(dst + 4) = __floats2bfloat162_rn(nx[q].z, nx[q].w);
            }
            // JIT transposed half
            {
                const float* xbn = x + ((size_t)nb_)*N_*N_*L_;
                #pragma unroll
                for (int q = 0; q < 3; q++){
                    const int idx = tid + q*1024;
                    const int p = idx / 12, c = idx % 12;
                    const int ti = p >> 4, tj = p & 15;
                    float4 u = *(const float4*)(xbn + ((size_t)(nj0+tj)*N_ + (ni0+ti))*L_ + c*4);
                    int posB = 48 + kposPair(c*4);
                    __nv_bfloat16* dst2 = Ab + p*AROW + posB;
                    *(__nv_bfloat162*)dst2       = __floats2bfloat162_rn(u.x, u.y);
                    *(__nv_bfloat162*)(dst2 + 4) = __floats2bfloat162_rn(u.z, u.w);
                }
            }
            // bias tiles for next tile
            #pragma unroll
            for (int q = 0; q < 3; q++){
                const int idx = tid + q*1024;
                if (idx < 1536){
                    const int rr = idx / 96, f = idx % 96;
                    bis[idx] = g_bi[(nb_*N_ + ni0 + rr)*F_ + f];
                } else {
                    const int ix = idx - 1536;
                    const int rr = ix / 96, f = ix % 96;
                    bjs_s[ix] = g_bjs[(nb_*N_ + nj0 + rr)*F_ + f];
                }
            }
            __syncthreads();
        }
    }
}

// ---------------- launch ----------------
extern "C" void kernel_launch(void* const* d_in, const int* in_sizes, int n_in,
                              void* d_out, int out_size){
    const float* x = (const float*)d_in[0];
    const float* w = (const float*)d_in[1];
    float* out = (float*)d_out;
    (void)in_sizes; (void)n_in; (void)out_size;

    const size_t smr = (size_t)(8*32*49 + 2*8*48) * sizeof(float);
    cudaFuncSetAttribute(k_reduce, cudaFuncAttributeMaxDynamicSharedMemorySize, (int)smr);
    k_reduce<<<dim3(NSTRIP, B_), 384, smr>>>(x);

    k_node<<<dim3(32, B_), 96>>>(w);

    const size_t smm = (size_t)(256*AROW + 96*BROW) * sizeof(__nv_bfloat16)
                     + (size_t)(2*16*96) * sizeof(float);   // 85504 B
    cudaFuncSetAttribute(k_main, cudaFuncAttributeMaxDynamicSharedMemorySize, (int)smm);
    k_main<<<GPERS, 1024, smm>>>(x, w, out);
}